// round 15
// baseline (speedup 1.0000x reference)
#include <cuda_runtime.h>
#include <cuda_bf16.h>

// ---------------------------------------------------------------------------
// Problem constants
// ---------------------------------------------------------------------------
#define NH    4          // heads
#define CH    64         // channels per head
#define HC    256        // NH*CH
#define NIN   300
#define NOUT  768
#define MAXN  50048
#define MAXE  800000
#define MAXG  1024
#define SLOPE_ATT 0.2f
#define SLOPE_ACT 0.01f

// ---------------------------------------------------------------------------
// Scratch (device globals; no allocation allowed)
// ---------------------------------------------------------------------------
__device__ uint4  g_hb4[MAXN * HC / 8];  // h in bf16 [N, HC] (uint4-aligned)
__device__ float  g_asrc[MAXN * NH];     // attention logits (plain stores)
__device__ float  g_adst[MAXN * NH];
__device__ int    g_cntn[MAXN];          // per-destination edge counts
__device__ int    g_off[MAXN + 1];       // CSR offsets
__device__ int    g_pos[MAXN];           // running slot counters
__device__ int    g_esrc[MAXE];          // CSR: source node per slot
__device__ float4 g_ew[MAXE];            // CSR: per-head weights per slot
__device__ float  g_pool[MAXG * HC];
__device__ float  g_cnt[MAXG];

// ---------------------------------------------------------------------------
// Helpers
// ---------------------------------------------------------------------------
__device__ __forceinline__ float lrelu(float v, float s) { return v > 0.0f ? v : s * v; }

__device__ __forceinline__ unsigned bf2u(__nv_bfloat162 v) {
    unsigned u; __builtin_memcpy(&u, &v, 4); return u;
}
__device__ __forceinline__ float2 u2f2(unsigned u) {
    __nv_bfloat162 b; __builtin_memcpy(&b, &u, 4);
    return __bfloat1622float2(b);
}
__device__ __forceinline__ void red_add_v4(float* p, float4 v) {
    asm volatile("red.global.add.v4.f32 [%0], {%1, %2, %3, %4};"
                 :: "l"(p), "f"(v.x), "f"(v.y), "f"(v.z), "f"(v.w) : "memory");
}

__device__ __forceinline__ void ldsm4(unsigned* r, unsigned addr) {
    asm volatile("ldmatrix.sync.aligned.m8n8.x4.shared.b16 {%0,%1,%2,%3}, [%4];"
                 : "=r"(r[0]), "=r"(r[1]), "=r"(r[2]), "=r"(r[3]) : "r"(addr));
}
__device__ __forceinline__ void ldsm4t(unsigned* r, unsigned addr) {
    asm volatile("ldmatrix.sync.aligned.m8n8.x4.trans.shared.b16 {%0,%1,%2,%3}, [%4];"
                 : "=r"(r[0]), "=r"(r[1]), "=r"(r[2]), "=r"(r[3]) : "r"(addr));
}
__device__ __forceinline__ void mma16816(float* c, const unsigned* a,
                                         unsigned b0, unsigned b1) {
    asm volatile("mma.sync.aligned.m16n8k16.row.col.f32.bf16.bf16.f32 "
                 "{%0,%1,%2,%3}, {%4,%5,%6,%7}, {%8,%9}, {%0,%1,%2,%3};"
                 : "+f"(c[0]), "+f"(c[1]), "+f"(c[2]), "+f"(c[3])
                 : "r"(a[0]), "r"(a[1]), "r"(a[2]), "r"(a[3]), "r"(b0), "r"(b1));
}

// ---------------------------------------------------------------------------
// K1: h = x @ lin_w on tensor cores (bf16 HMMA, 3-term hi/lo split).
// 128x256 tile, BK=16, 512 threads, warp tile 32x64 (warp-col == head).
// Fused epilogue: attention logits (plain stores) + staged bf16 h write.
// ---------------------------------------------------------------------------
#define ASTR 24    // A smem row stride in halfs (48 B)
#define BSTR 264   // B smem row stride in halfs (528 B)

__global__ void __launch_bounds__(512, 1)
k_gemm_mma(const float* __restrict__ x, const float* __restrict__ w,
           const float* __restrict__ att_src, const float* __restrict__ att_dst,
           int Ntot) {
    __shared__ __align__(16) char smem_raw[33792];
    __nv_bfloat16* sA_hi = (__nv_bfloat16*)(smem_raw);
    __nv_bfloat16* sA_lo = (__nv_bfloat16*)(smem_raw + 6144);
    __nv_bfloat16* sB_hi = (__nv_bfloat16*)(smem_raw + 12288);
    __nv_bfloat16* sB_lo = (__nv_bfloat16*)(smem_raw + 20736);

    const int t    = threadIdx.x;
    const int lane = t & 31;
    const int wid  = t >> 5;
    const int wm   = wid >> 2;
    const int wn   = wid & 3;
    const int m0   = blockIdx.x * 128;

    const int arow = t >> 2;
    const int akq  = (t & 3) * 4;
    const int bkr  = t >> 5;
    const int bc   = (t & 31) * 8;

    float acc[2][8][4];
#pragma unroll
    for (int f = 0; f < 2; f++)
#pragma unroll
        for (int j = 0; j < 8; j++)
#pragma unroll
            for (int q = 0; q < 4; q++) acc[f][j][q] = 0.0f;

    const unsigned baseAhi = (unsigned)__cvta_generic_to_shared(sA_hi);
    const unsigned baseAlo = (unsigned)__cvta_generic_to_shared(sA_lo);
    const unsigned baseBhi = (unsigned)__cvta_generic_to_shared(sB_hi);
    const unsigned baseBlo = (unsigned)__cvta_generic_to_shared(sB_lo);
    unsigned aAhi[2], aAlo[2], aBhi[4], aBlo[4];
    {
        const int ar  = (lane & 15);
        const int ach = (lane >> 4) * 8;
#pragma unroll
        for (int f = 0; f < 2; f++) {
            const int off = ((wm * 32 + f * 16 + ar) * ASTR + ach) * 2;
            aAhi[f] = baseAhi + off;
            aAlo[f] = baseAlo + off;
        }
        const int mat  = lane >> 3;
        const int bkrw = (lane & 7) + ((mat & 1) << 3);
        const int bnof = (mat >> 1) * 8;
#pragma unroll
        for (int p = 0; p < 4; p++) {
            const int off = (bkrw * BSTR + wn * 64 + p * 16 + bnof) * 2;
            aBhi[p] = baseBhi + off;
            aBlo[p] = baseBlo + off;
        }
    }

    const int nk = 19;
    float4 ra, rb0, rb1;

    {
        ra = make_float4(0.f, 0.f, 0.f, 0.f);
        const int m = m0 + arow;
        if (m < Ntot && akq + 3 < NIN)
            ra = *(const float4*)(x + (size_t)m * NIN + akq);
        rb0 = make_float4(0.f, 0.f, 0.f, 0.f);
        rb1 = make_float4(0.f, 0.f, 0.f, 0.f);
        if (bkr < NIN) {
            rb0 = *(const float4*)(w + (size_t)bkr * HC + bc);
            rb1 = *(const float4*)(w + (size_t)bkr * HC + bc + 4);
        }
    }

    for (int kt = 0; kt < nk; kt++) {
        __syncthreads();
        {
            float av[4] = {ra.x, ra.y, ra.z, ra.w};
            __nv_bfloat16 hi[4], lo[4];
#pragma unroll
            for (int q = 0; q < 4; q++) {
                hi[q] = __float2bfloat16_rn(av[q]);
                lo[q] = __float2bfloat16_rn(av[q] - __bfloat162float(hi[q]));
            }
            uint2 uh, ul;
            uh.x = bf2u(__nv_bfloat162{hi[0], hi[1]});
            uh.y = bf2u(__nv_bfloat162{hi[2], hi[3]});
            ul.x = bf2u(__nv_bfloat162{lo[0], lo[1]});
            ul.y = bf2u(__nv_bfloat162{lo[2], lo[3]});
            *(uint2*)(sA_hi + arow * ASTR + akq) = uh;
            *(uint2*)(sA_lo + arow * ASTR + akq) = ul;

            float bv[8] = {rb0.x, rb0.y, rb0.z, rb0.w, rb1.x, rb1.y, rb1.z, rb1.w};
            __nv_bfloat16 bh[8], blo[8];
#pragma unroll
            for (int q = 0; q < 8; q++) {
                bh[q]  = __float2bfloat16_rn(bv[q]);
                blo[q] = __float2bfloat16_rn(bv[q] - __bfloat162float(bh[q]));
            }
            uint4 vh, vl;
            vh.x = bf2u(__nv_bfloat162{bh[0], bh[1]});
            vh.y = bf2u(__nv_bfloat162{bh[2], bh[3]});
            vh.z = bf2u(__nv_bfloat162{bh[4], bh[5]});
            vh.w = bf2u(__nv_bfloat162{bh[6], bh[7]});
            vl.x = bf2u(__nv_bfloat162{blo[0], blo[1]});
            vl.y = bf2u(__nv_bfloat162{blo[2], blo[3]});
            vl.z = bf2u(__nv_bfloat162{blo[4], blo[5]});
            vl.w = bf2u(__nv_bfloat162{blo[6], blo[7]});
            *(uint4*)(sB_hi + bkr * BSTR + bc) = vh;
            *(uint4*)(sB_lo + bkr * BSTR + bc) = vl;
        }
        __syncthreads();

        if (kt + 1 < nk) {
            const int kb = (kt + 1) * 16;
            ra = make_float4(0.f, 0.f, 0.f, 0.f);
            const int m = m0 + arow;
            const int ka = kb + akq;
            if (m < Ntot && ka + 3 < NIN)
                ra = *(const float4*)(x + (size_t)m * NIN + ka);
            rb0 = make_float4(0.f, 0.f, 0.f, 0.f);
            rb1 = make_float4(0.f, 0.f, 0.f, 0.f);
            const int kw = kb + bkr;
            if (kw < NIN) {
                rb0 = *(const float4*)(w + (size_t)kw * HC + bc);
                rb1 = *(const float4*)(w + (size_t)kw * HC + bc + 4);
            }
        }

        unsigned a_hi[2][4], a_lo[2][4];
#pragma unroll
        for (int f = 0; f < 2; f++) {
            ldsm4(a_hi[f], aAhi[f]);
            ldsm4(a_lo[f], aAlo[f]);
        }
#pragma unroll
        for (int p = 0; p < 4; p++) {
            unsigned bh[4];
            ldsm4t(bh, aBhi[p]);
#pragma unroll
            for (int f = 0; f < 2; f++) {
                mma16816(acc[f][2 * p],     a_hi[f], bh[0], bh[1]);
                mma16816(acc[f][2 * p + 1], a_hi[f], bh[2], bh[3]);
                mma16816(acc[f][2 * p],     a_lo[f], bh[0], bh[1]);
                mma16816(acc[f][2 * p + 1], a_lo[f], bh[2], bh[3]);
            }
            unsigned bl[4];
            ldsm4t(bl, aBlo[p]);
#pragma unroll
            for (int f = 0; f < 2; f++) {
                mma16816(acc[f][2 * p],     a_hi[f], bl[0], bl[1]);
                mma16816(acc[f][2 * p + 1], a_hi[f], bl[2], bl[3]);
            }
        }
    }

    // ---------------- epilogue: attention logits (plain stores) ----------------
    const int nb = wn * 64;
    const int qc = (lane & 3) * 2;
    float2 sv[8], dv[8];
#pragma unroll
    for (int j = 0; j < 8; j++) {
        sv[j] = *(const float2*)(att_src + nb + j * 8 + qc);
        dv[j] = *(const float2*)(att_dst + nb + j * 8 + qc);
    }
#pragma unroll
    for (int f = 0; f < 2; f++) {
        float ps0 = 0.f, pd0 = 0.f, ps1 = 0.f, pd1 = 0.f;
#pragma unroll
        for (int j = 0; j < 8; j++) {
            ps0 += acc[f][j][0] * sv[j].x + acc[f][j][1] * sv[j].y;
            pd0 += acc[f][j][0] * dv[j].x + acc[f][j][1] * dv[j].y;
            ps1 += acc[f][j][2] * sv[j].x + acc[f][j][3] * sv[j].y;
            pd1 += acc[f][j][2] * dv[j].x + acc[f][j][3] * dv[j].y;
        }
#pragma unroll
        for (int msk = 1; msk < 4; msk <<= 1) {
            ps0 += __shfl_xor_sync(0xffffffffu, ps0, msk);
            pd0 += __shfl_xor_sync(0xffffffffu, pd0, msk);
            ps1 += __shfl_xor_sync(0xffffffffu, ps1, msk);
            pd1 += __shfl_xor_sync(0xffffffffu, pd1, msk);
        }
        const int r0 = m0 + wm * 32 + f * 16 + (lane >> 2);
        const int r1 = r0 + 8;
        if ((lane & 3) == 0) {
            if (r0 < Ntot) { g_asrc[r0 * NH + wn] = ps0; g_adst[r0 * NH + wn] = pd0; }
            if (r1 < Ntot) { g_asrc[r1 * NH + wn] = ps1; g_adst[r1 * NH + wn] = pd1; }
        }
    }

    // ---------------- epilogue: staged bf16 h store (coalesced) ----------------
    unsigned* stg = (unsigned*)smem_raw;   // 64 rows x 132 uints
#pragma unroll
    for (int half = 0; half < 2; half++) {
        __syncthreads();
        if ((wm >> 1) == half) {
            const int srb = (wm & 1) * 32;
#pragma unroll
            for (int f = 0; f < 2; f++) {
                const int sr0 = srb + f * 16 + (lane >> 2);
#pragma unroll
                for (int j = 0; j < 8; j++) {
                    const int cu = (nb >> 1) + j * 4 + (lane & 3);
                    stg[sr0 * 132 + cu] =
                        bf2u(__floats2bfloat162_rn(acc[f][j][0], acc[f][j][1]));
                    stg[(sr0 + 8) * 132 + cu] =
                        bf2u(__floats2bfloat162_rn(acc[f][j][2], acc[f][j][3]));
                }
            }
        }
        __syncthreads();
        const int r  = t >> 3;
        const int gr = m0 + half * 64 + r;
        if (gr < Ntot) {
            const uint4* srow = (const uint4*)(stg + r * 132);
            uint4* drow = g_hb4 + (size_t)gr * 32;
#pragma unroll
            for (int i = 0; i < 4; i++) {
                const int c4 = (t & 7) + i * 8;
                drow[c4] = srow[c4];
            }
        }
    }
}

// ---------------------------------------------------------------------------
// K0: zero accumulators (pool, counts, per-dst counters)
// ---------------------------------------------------------------------------
__global__ void k_zero(int Gtot, int Ntot) {
    const int i = blockIdx.x * blockDim.x + threadIdx.x;
    if (i < Gtot * HC) g_pool[i] = 0.0f;
    if (i < Gtot) g_cnt[i] = 0.0f;
    if (i < Ntot) g_cntn[i] = 0;
}

// ---------------------------------------------------------------------------
// K2: per-destination edge count
// ---------------------------------------------------------------------------
__global__ void k_count(const int* __restrict__ ei, int E) {
    const int e = blockIdx.x * blockDim.x + threadIdx.x;
    if (e < E) atomicAdd(&g_cntn[ei[E + e]], 1);
}

// ---------------------------------------------------------------------------
// K3: fused single-block exclusive scan (1024 threads, ~49 elems/thread).
// Phase A: thread-chunk sums + warp/block shfl scan. Phase B: re-read chunk
// (L2-hot), emit running offsets into g_off and g_pos.
// ---------------------------------------------------------------------------
__global__ void __launch_bounds__(1024) k_scan(int Ntot) {
    __shared__ int ws[32];
    const int t = threadIdx.x;
    const int C = (Ntot + 1023) / 1024;
    const int lo = t * C;
    const int hi = min(lo + C, Ntot);

    int sum = 0;
    for (int i = lo; i < hi; i++) sum += g_cntn[i];

    // warp inclusive scan
    int inc = sum;
#pragma unroll
    for (int o = 1; o < 32; o <<= 1) {
        int v = __shfl_up_sync(0xffffffffu, inc, o);
        if ((t & 31) >= o) inc += v;
    }
    if ((t & 31) == 31) ws[t >> 5] = inc;
    __syncthreads();
    if (t < 32) {
        int v = ws[t];
        int wi = v;
#pragma unroll
        for (int o = 1; o < 32; o <<= 1) {
            int u = __shfl_up_sync(0xffffffffu, wi, o);
            if (t >= o) wi += u;
        }
        ws[t] = wi - v;   // exclusive warp base
    }
    __syncthreads();
    int base = (inc - sum) + ws[t >> 5];   // exclusive prefix for this thread

    if (t == 1023) g_off[Ntot] = base + sum;   // total = E

    int run = base;
    for (int i = lo; i < hi; i++) {
        g_off[i] = run;
        g_pos[i] = run;
        run += g_cntn[i];
    }
}

// ---------------------------------------------------------------------------
// K4: edge scatter into CSR slots (weights precomputed per edge)
// ---------------------------------------------------------------------------
__global__ void k_scatter(const int* __restrict__ ei, int E) {
    const int e = blockIdx.x * blockDim.x + threadIdx.x;
    if (e >= E) return;
    const int s = __ldg(ei + e);
    const int d = __ldg(ei + E + e);
    float4 as = *(const float4*)(g_asrc + s * NH);
    float4 ad = *(const float4*)(g_adst + d * NH);
    float4 wv;
    wv.x = __expf(lrelu(as.x + ad.x, SLOPE_ATT));
    wv.y = __expf(lrelu(as.y + ad.y, SLOPE_ATT));
    wv.z = __expf(lrelu(as.z + ad.z, SLOPE_ATT));
    wv.w = __expf(lrelu(as.w + ad.w, SLOPE_ATT));
    const int slot = atomicAdd(&g_pos[d], 1);
    g_esrc[slot] = s;
    g_ew[slot]   = wv;
}

// ---------------------------------------------------------------------------
// K5: pull-mode aggregation + fused mean-pool — one warp per node.
// bf16 gather, edge loop x2-unrolled; finalized row red.add'ed directly
// into g_pool[batch[n]] (no g_o round-trip, no separate pool kernel).
// ---------------------------------------------------------------------------
__global__ void __launch_bounds__(256) k_node_agg(const int* __restrict__ batch,
                                                  const float* __restrict__ bias,
                                                  int Ntot) {
    const int n    = (blockIdx.x * blockDim.x + threadIdx.x) >> 5;
    const int lane = threadIdx.x & 31;
    if (n >= Ntot) return;

    const int hlo = lane >> 4;
    const int hhi = hlo + 2;

    float es0 = __expf(lrelu(g_asrc[n * NH + hlo] + g_adst[n * NH + hlo], SLOPE_ATT));
    float es1 = __expf(lrelu(g_asrc[n * NH + hhi] + g_adst[n * NH + hhi], SLOPE_ATT));

    const uint2* hb = (const uint2*)g_hb4;
    uint2 su0 = hb[(size_t)n * 64 + lane];
    uint2 su1 = hb[(size_t)n * 64 + 32 + lane];
    float2 fa = u2f2(su0.x), fb = u2f2(su0.y);
    float2 fc = u2f2(su1.x), fd = u2f2(su1.y);

    float4 acc0 = make_float4(fa.x * es0, fa.y * es0, fb.x * es0, fb.y * es0);
    float4 acc1 = make_float4(fc.x * es1, fc.y * es1, fd.x * es1, fd.y * es1);
    float den0 = es0, den1 = es1;

    const int beg = g_off[n];
    const int end = g_off[n + 1];

    int i = beg;
    for (; i + 2 <= end; i += 2) {
        const int sA = g_esrc[i];
        const int sB = g_esrc[i + 1];
        const float4 wA = g_ew[i];
        const float4 wB = g_ew[i + 1];

        uint2 uA0 = hb[(size_t)sA * 64 + lane];
        uint2 uA1 = hb[(size_t)sA * 64 + 32 + lane];
        uint2 uB0 = hb[(size_t)sB * 64 + lane];
        uint2 uB1 = hb[(size_t)sB * 64 + 32 + lane];

        const float eA0 = (lane < 16) ? wA.x : wA.y;
        const float eA1 = (lane < 16) ? wA.z : wA.w;
        const float eB0 = (lane < 16) ? wB.x : wB.y;
        const float eB1 = (lane < 16) ? wB.z : wB.w;

        float2 v0 = u2f2(uA0.x), v1 = u2f2(uA0.y);
        float2 v2 = u2f2(uA1.x), v3 = u2f2(uA1.y);
        acc0.x += v0.x * eA0; acc0.y += v0.y * eA0;
        acc0.z += v1.x * eA0; acc0.w += v1.y * eA0;
        acc1.x += v2.x * eA1; acc1.y += v2.y * eA1;
        acc1.z += v3.x * eA1; acc1.w += v3.y * eA1;

        v0 = u2f2(uB0.x); v1 = u2f2(uB0.y);
        v2 = u2f2(uB1.x); v3 = u2f2(uB1.y);
        acc0.x += v0.x * eB0; acc0.y += v0.y * eB0;
        acc0.z += v1.x * eB0; acc0.w += v1.y * eB0;
        acc1.x += v2.x * eB1; acc1.y += v2.y * eB1;
        acc1.z += v3.x * eB1; acc1.w += v3.y * eB1;

        den0 += eA0 + eB0; den1 += eA1 + eB1;
    }
    if (i < end) {
        const int sA = g_esrc[i];
        const float4 wA = g_ew[i];
        uint2 uA0 = hb[(size_t)sA * 64 + lane];
        uint2 uA1 = hb[(size_t)sA * 64 + 32 + lane];
        const float eA0 = (lane < 16) ? wA.x : wA.y;
        const float eA1 = (lane < 16) ? wA.z : wA.w;
        float2 v0 = u2f2(uA0.x), v1 = u2f2(uA0.y);
        float2 v2 = u2f2(uA1.x), v3 = u2f2(uA1.y);
        acc0.x += v0.x * eA0; acc0.y += v0.y * eA0;
        acc0.z += v1.x * eA0; acc0.w += v1.y * eA0;
        acc1.x += v2.x * eA1; acc1.y += v2.y * eA1;
        acc1.z += v3.x * eA1; acc1.w += v3.y * eA1;
        den0 += eA0; den1 += eA1;
    }

    const float inv0 = 1.0f / den0;
    const float inv1 = 1.0f / den1;
    const float4 bb0 = *(const float4*)(bias + lane * 4);
    const float4 bb1 = *(const float4*)(bias + 128 + lane * 4);

    float4 o0 = make_float4(lrelu(acc0.x * inv0 + bb0.x, SLOPE_ACT),
                            lrelu(acc0.y * inv0 + bb0.y, SLOPE_ACT),
                            lrelu(acc0.z * inv0 + bb0.z, SLOPE_ACT),
                            lrelu(acc0.w * inv0 + bb0.w, SLOPE_ACT));
    float4 o1 = make_float4(lrelu(acc1.x * inv1 + bb1.x, SLOPE_ACT),
                            lrelu(acc1.y * inv1 + bb1.y, SLOPE_ACT),
                            lrelu(acc1.z * inv1 + bb1.z, SLOPE_ACT),
                            lrelu(acc1.w * inv1 + bb1.w, SLOPE_ACT));

    // fused mean-pool: accumulate directly into this node's graph row
    const int b = batch[n];
    float* pp = g_pool + (size_t)b * HC + lane * 4;
    red_add_v4(pp,       o0);
    red_add_v4(pp + 128, o1);
    if (lane == 0) atomicAdd(&g_cnt[b], 1.0f);
}

// ---------------------------------------------------------------------------
// K7: final GEMM  out[G,768] = (pool/cnt) @ fc1_w + fc1_b
// ---------------------------------------------------------------------------
__global__ void __launch_bounds__(256) k_final(const float* __restrict__ fw,
                                               const float* __restrict__ fb,
                                               float* __restrict__ out, int G) {
    __shared__ float p[16][HC];
    const int g0 = blockIdx.x * 16;
    const int j0 = blockIdx.y * 128;
    const int t  = threadIdx.x;

    for (int i = t; i < 16 * HC; i += 256) {
        const int g = i / HC, k = i % HC;
        float val = 0.0f;
        if (g0 + g < G) {
            float c = fmaxf(g_cnt[g0 + g], 1.0f);
            val = g_pool[(size_t)(g0 + g) * HC + k] / c;
        }
        p[g][k] = val;
    }
    __syncthreads();

    const int j  = j0 + (t & 127);
    const int gg = t >> 7;
    float acc[8];
#pragma unroll
    for (int r = 0; r < 8; r++) acc[r] = 0.0f;

    for (int k = 0; k < HC; k++) {
        float wv = fw[(size_t)k * NOUT + j];
#pragma unroll
        for (int r = 0; r < 8; r++) acc[r] += p[gg + r * 2][k] * wv;
    }
    float bv = fb[j];
#pragma unroll
    for (int r = 0; r < 8; r++) {
        const int g = g0 + gg + r * 2;
        if (g < G) out[(size_t)g * NOUT + j] = acc[r] + bv;
    }
}

// ---------------------------------------------------------------------------
// launch
// ---------------------------------------------------------------------------
extern "C" void kernel_launch(void* const* d_in, const int* in_sizes, int n_in,
                              void* d_out, int out_size) {
    const float* x       = (const float*)d_in[0];
    const int*   ei      = (const int*)d_in[1];
    const int*   batch   = (const int*)d_in[2];
    const float* lin_w   = (const float*)d_in[3];
    const float* att_src = (const float*)d_in[4];
    const float* att_dst = (const float*)d_in[5];
    const float* bias    = (const float*)d_in[6];
    const float* fc1_w   = (const float*)d_in[7];
    const float* fc1_b   = (const float*)d_in[8];
    float* out = (float*)d_out;

    const int N = in_sizes[0] / NIN;
    const int E = in_sizes[1] / 2;
    const int G = out_size / NOUT;

    const int zeroElems = (G * HC > N) ? G * HC : N;
    k_zero<<<(zeroElems + 255) / 256, 256>>>(G, N);

    k_count<<<(E + 255) / 256, 256>>>(ei, E);
    k_scan<<<1, 1024>>>(N);

    k_gemm_mma<<<(N + 127) / 128, 512>>>(x, lin_w, att_src, att_dst, N);

    k_scatter<<<(E + 255) / 256, 256>>>(ei, E);
    k_node_agg<<<(N + 7) / 8, 256>>>(batch, bias, N);

    dim3 fin_grid((G + 15) / 16, NOUT / 128);
    k_final<<<fin_grid, 256>>>(fc1_w, fc1_b, out, G);
}